// round 9
// baseline (speedup 1.0000x reference)
#include <cuda_runtime.h>

typedef unsigned long long ull;

#define BB 64
#define NN 16
#define TT 128
#define HH 256
#define NP1 17
#define NPAIRS (BB*NP1)   // 1088
#define LDT 132           // padded smem row stride in floats (528B, 16B-aligned)

// ---------------- scratch (static device globals; no runtime allocation) ----------------
__device__ float g_q  [BB*TT*HH];     // node @ Wq^T
__device__ float g_t2 [BB*TT*HH];     // q @ Wb
__device__ float g_P  [BB*TT*HH];     // (q @ Wb) @ Wk
__device__ float g_Afb[(size_t)NPAIRS*TT*TT]; // fallback A buffer if A is not part of d_out

// ---------------- f32x2 helpers (Blackwell packed fp32, 2x FFMA throughput) -------------
__device__ __forceinline__ void fma2(ull& d, ull a, ull b){
    asm("fma.rn.f32x2 %0, %1, %2, %0;" : "+l"(d) : "l"(a), "l"(b));
}
__device__ __forceinline__ ull pk2(float x, float y){
    ull r; asm("mov.b64 %0, {%1, %2};" : "=l"(r) : "f"(x), "f"(y)); return r;
}
__device__ __forceinline__ float2 upk(ull v){
    float2 f; asm("mov.b64 {%0, %1}, %2;" : "=f"(f.x), "=f"(f.y) : "l"(v)); return f;
}

// ---------------- split staging: LDG into regs (prefetch) / STS after compute ----------
struct F8 { float4 a, b; };

// transpose path: smem[k][i] = src[i*ld + k]
__device__ __forceinline__ F8 ldg_T(const float* __restrict__ src, int ld, int tid){
    int c4 = (tid & 3) * 4;   // k offset (float4 group)
    int r  = tid >> 2;        // 0..63
    F8 f;
    f.a = *(const float4*)(src + (size_t)r*ld + c4);
    f.b = *(const float4*)(src + (size_t)(r+64)*ld + c4);
    return f;
}
__device__ __forceinline__ void sts_T(float (*dst)[LDT], F8 f, int tid){
    int c4 = (tid & 3) * 4;
    int r  = tid >> 2;
    dst[c4+0][r]    = f.a.x; dst[c4+1][r]    = f.a.y;
    dst[c4+2][r]    = f.a.z; dst[c4+3][r]    = f.a.w;
    dst[c4+0][r+64] = f.b.x; dst[c4+1][r+64] = f.b.y;
    dst[c4+2][r+64] = f.b.z; dst[c4+3][r+64] = f.b.w;
}
// direct path: smem[k][n] = src[k*ld + n]
__device__ __forceinline__ F8 ldg_D(const float* __restrict__ src, int ld, int tid){
    int n4 = (tid & 15) * 4;
    int k  = tid >> 4;        // 0..15
    F8 f;
    f.a = *(const float4*)(src + (size_t)k*ld + n4);
    f.b = *(const float4*)(src + (size_t)k*ld + n4 + 64);
    return f;
}
__device__ __forceinline__ void sts_D(float (*dst)[LDT], F8 f, int tid){
    int n4 = (tid & 15) * 4;
    int k  = tid >> 4;
    *(float4*)(&dst[k][n4])      = f.a;
    *(float4*)(&dst[k][n4 + 64]) = f.b;
}

// ---------------- 128x128 tile micro-kernel, one BK=16 slab ----------------
__device__ __forceinline__ void mm16(ull acc[8][4], const float (*As)[LDT],
                                     const float (*Bs)[LDT], int tx, int ty){
    #pragma unroll
    for (int k = 0; k < 16; ++k){
        float4 a0 = *(const float4*)(&As[k][ty*4]);
        float4 a1 = *(const float4*)(&As[k][64+ty*4]);
        float4 b0 = *(const float4*)(&Bs[k][tx*4]);
        float4 b1 = *(const float4*)(&Bs[k][64+tx*4]);
        ull bb0 = pk2(b0.x,b0.y), bb1 = pk2(b0.z,b0.w);
        ull bb2 = pk2(b1.x,b1.y), bb3 = pk2(b1.z,b1.w);
        float av[8] = {a0.x,a0.y,a0.z,a0.w,a1.x,a1.y,a1.z,a1.w};
        #pragma unroll
        for (int i = 0; i < 8; ++i){
            ull ad = pk2(av[i], av[i]);
            fma2(acc[i][0], ad, bb0);
            fma2(acc[i][1], ad, bb1);
            fma2(acc[i][2], ad, bb2);
            fma2(acc[i][3], ad, bb3);
        }
    }
}

__device__ __forceinline__ int row_of(int i, int ty){
    return (i < 4) ? (ty*4 + i) : (64 + ty*4 + (i-4));
}

__device__ __forceinline__ const float* pair_base(int p, const float* node, const float* neigh){
    int b = p / NP1, n = p % NP1;
    return (n == 0) ? node  + (size_t)b*TT*HH
                    : neigh + (size_t)(b*NN + (n-1))*TT*HH;
}

// ================= K1..K3: flat [8192,256] x [256,256] GEMM chain ========================
template<int STEP>
__global__ void __launch_bounds__(256, 2) sgemm_flat(const float* __restrict__ Ain,
                                                     const float* __restrict__ W){
    __shared__ __align__(16) float As[2][16][LDT], Bs[2][16][LDT];
    int tid = threadIdx.x, tx = tid & 15, ty = tid >> 4;
    const float* A = (STEP == 0) ? Ain : (STEP == 1 ? g_q : g_t2);
    float*       C = (STEP == 0) ? g_q : (STEP == 1 ? g_t2 : g_P);
    const float* Ab = A + (size_t)blockIdx.x * 128 * HH;
    int n0 = blockIdx.y * 128;
    const float* Bb = (STEP == 0) ? W + (size_t)n0*HH : W + n0;

    ull acc[8][4];
    #pragma unroll
    for (int i=0;i<8;i++){ acc[i][0]=acc[i][1]=acc[i][2]=acc[i][3]=0ULL; }

    F8 ra = ldg_T(Ab, HH, tid);
    F8 rb = (STEP == 0) ? ldg_T(Bb, HH, tid) : ldg_D(Bb, HH, tid);
    sts_T(As[0], ra, tid);
    if (STEP == 0) sts_T(Bs[0], rb, tid); else sts_D(Bs[0], rb, tid);
    __syncthreads();

    #pragma unroll 2
    for (int s = 0; s < 16; ++s){
        if (s < 15){
            ra = ldg_T(Ab + (s+1)*16, HH, tid);
            rb = (STEP == 0) ? ldg_T(Bb + (s+1)*16, HH, tid)
                             : ldg_D(Bb + (size_t)(s+1)*16*HH, HH, tid);
        }
        mm16(acc, As[s&1], Bs[s&1], tx, ty);
        if (s < 15){
            sts_T(As[(s+1)&1], ra, tid);
            if (STEP == 0) sts_T(Bs[(s+1)&1], rb, tid); else sts_D(Bs[(s+1)&1], rb, tid);
        }
        __syncthreads();
    }

    float* Cb = C + (size_t)blockIdx.x*128*HH + n0;
    #pragma unroll
    for (int i=0;i<8;i++){
        int row = row_of(i, ty);
        float2 p0=upk(acc[i][0]), p1=upk(acc[i][1]), p2=upk(acc[i][2]), p3=upk(acc[i][3]);
        *(float4*)(Cb + (size_t)row*HH + tx*4)      = make_float4(p0.x,p0.y,p1.x,p1.y);
        *(float4*)(Cb + (size_t)row*HH + 64 + tx*4) = make_float4(p2.x,p2.y,p3.x,p3.y);
    }
}

// ================= K4: S = P_b @ X_p^T  (+bias) -> softmax -> A ==========================
__global__ void __launch_bounds__(256, 2) kernel_S(const float* __restrict__ node,
                                                   const float* __restrict__ neigh,
                                                   const float* __restrict__ bias,
                                                   float* Aout){
    __shared__ __align__(16) float As[2][16][LDT], Bs[2][16][LDT];
    int tid = threadIdx.x, tx = tid & 15, ty = tid >> 4;
    int p = blockIdx.x, b = p / NP1;
    const float* Pb = g_P + (size_t)b*TT*HH;
    const float* X  = pair_base(p, node, neigh);
    float* Ao = (Aout != nullptr) ? Aout : g_Afb;

    ull acc[8][4];
    #pragma unroll
    for (int i=0;i<8;i++){ acc[i][0]=acc[i][1]=acc[i][2]=acc[i][3]=0ULL; }

    F8 ra = ldg_T(Pb, HH, tid);
    F8 rb = ldg_T(X,  HH, tid);
    sts_T(As[0], ra, tid);
    sts_T(Bs[0], rb, tid);
    __syncthreads();

    #pragma unroll 2
    for (int s = 0; s < 16; ++s){
        if (s < 15){
            ra = ldg_T(Pb + (s+1)*16, HH, tid);
            rb = ldg_T(X  + (s+1)*16, HH, tid);
        }
        mm16(acc, As[s&1], Bs[s&1], tx, ty);
        if (s < 15){
            sts_T(As[(s+1)&1], ra, tid);
            sts_T(Bs[(s+1)&1], rb, tid);
        }
        __syncthreads();
    }

    // unpack S, add bias (broadcast over s), softmax over s (cols of the tile)
    float v[8][8];
    #pragma unroll
    for (int i=0;i<8;i++){
        float2 p0=upk(acc[i][0]), p1=upk(acc[i][1]), p2=upk(acc[i][2]), p3=upk(acc[i][3]);
        v[i][0]=p0.x; v[i][1]=p0.y; v[i][2]=p1.x; v[i][3]=p1.y;
        v[i][4]=p2.x; v[i][5]=p2.y; v[i][6]=p3.x; v[i][7]=p3.y;
    }
    float4 bb0 = *(const float4*)(bias + tx*4);
    float4 bb1 = *(const float4*)(bias + 64 + tx*4);
    float bv[8] = {bb0.x,bb0.y,bb0.z,bb0.w, bb1.x,bb1.y,bb1.z,bb1.w};

    float* Ap = Ao + (size_t)p*TT*TT;
    #pragma unroll
    for (int i=0;i<8;i++){
        #pragma unroll
        for (int j=0;j<8;j++) v[i][j] += bv[j];
        float m = v[i][0];
        #pragma unroll
        for (int j=1;j<8;j++) m = fmaxf(m, v[i][j]);
        #pragma unroll
        for (int o=8;o>=1;o>>=1) m = fmaxf(m, __shfl_xor_sync(0xffffffffu, m, o));
        float s = 0.f;
        #pragma unroll
        for (int j=0;j<8;j++){ v[i][j] = __expf(v[i][j] - m); s += v[i][j]; }
        #pragma unroll
        for (int o=8;o>=1;o>>=1) s += __shfl_xor_sync(0xffffffffu, s, o);
        float r = 1.f / s;
        int row = row_of(i, ty);
        *(float4*)(Ap + (size_t)row*TT + tx*4) =
            make_float4(v[i][0]*r, v[i][1]*r, v[i][2]*r, v[i][3]*r);
        *(float4*)(Ap + (size_t)row*TT + 64 + tx*4) =
            make_float4(v[i][4]*r, v[i][5]*r, v[i][6]*r, v[i][7]*r);
    }
}

// ================= K5: fused V = X_p @ Wv^T (tile in smem), then O = A @ V ===============
__global__ void __launch_bounds__(256, 2) kernel_VO(const float* __restrict__ node,
                                                    const float* __restrict__ neigh,
                                                    const float* __restrict__ Wv,
                                                    const float* Ain,
                                                    float* __restrict__ Out){
    extern __shared__ float sm[];
    float (*Vs)[LDT]      = (float (*)[LDT])sm;                             // 128xLDT
    float (*As2)[16][LDT] = (float (*)[16][LDT])(sm + 128*LDT);             // 2 bufs
    float (*Bs2)[16][LDT] = (float (*)[16][LDT])(sm + 128*LDT + 2*16*LDT);  // 2 bufs

    int tid = threadIdx.x, tx = tid & 15, ty = tid >> 4;
    int p = blockIdx.x;
    int n0 = blockIdx.y * 128;       // H column chunk
    const float* X  = pair_base(p, node, neigh);
    const float* Wb = Wv + (size_t)n0*HH;
    const float* Ap = ((Ain != nullptr) ? Ain : (const float*)g_Afb) + (size_t)p*TT*TT;

    ull acc[8][4];
    #pragma unroll
    for (int i=0;i<8;i++){ acc[i][0]=acc[i][1]=acc[i][2]=acc[i][3]=0ULL; }

    // ---- GEMM1: Vtile[s, c] = sum_k X[s,k] * Wv[n0+c, k] ----
    {
        F8 ra = ldg_T(X,  HH, tid);
        F8 rb = ldg_T(Wb, HH, tid);
        sts_T(As2[0], ra, tid);
        sts_T(Bs2[0], rb, tid);
        __syncthreads();
        #pragma unroll 2
        for (int s = 0; s < 16; ++s){
            if (s < 15){
                ra = ldg_T(X  + (s+1)*16, HH, tid);
                rb = ldg_T(Wb + (s+1)*16, HH, tid);
            }
            mm16(acc, As2[s&1], Bs2[s&1], tx, ty);
            if (s < 15){
                sts_T(As2[(s+1)&1], ra, tid);
                sts_T(Bs2[(s+1)&1], rb, tid);
            }
            __syncthreads();
        }
    }
    // write Vtile to smem, reset acc, prefetch GEMM2 slab 0 (As2[0] is free after last sync)
    #pragma unroll
    for (int i=0;i<8;i++){
        int row = row_of(i, ty);
        float2 p0=upk(acc[i][0]), p1=upk(acc[i][1]), p2=upk(acc[i][2]), p3=upk(acc[i][3]);
        *(float4*)(&Vs[row][tx*4])    = make_float4(p0.x,p0.y,p1.x,p1.y);
        *(float4*)(&Vs[row][64+tx*4]) = make_float4(p2.x,p2.y,p3.x,p3.y);
        acc[i][0]=acc[i][1]=acc[i][2]=acc[i][3]=0ULL;
    }
    {
        F8 ra = ldg_T(Ap, TT, tid);
        sts_T(As2[0], ra, tid);
    }
    __syncthreads();

    // ---- GEMM2: O[t, c] = sum_s A[t,s] * Vs[s][c]  (K = 128, B resident in smem) ----
    #pragma unroll 2
    for (int s = 0; s < 8; ++s){
        F8 ra;
        if (s < 7) ra = ldg_T(Ap + (s+1)*16, TT, tid);
        mm16(acc, As2[s&1], Vs + s*16, tx, ty);
        if (s < 7) sts_T(As2[(s+1)&1], ra, tid);
        __syncthreads();
    }

    float* Ob = Out + (size_t)p*TT*HH + n0;
    #pragma unroll
    for (int i=0;i<8;i++){
        int row = row_of(i, ty);
        float2 p0=upk(acc[i][0]), p1=upk(acc[i][1]), p2=upk(acc[i][2]), p3=upk(acc[i][3]);
        *(float4*)(Ob + (size_t)row*HH + tx*4)      = make_float4(p0.x,p0.y,p1.x,p1.y);
        *(float4*)(Ob + (size_t)row*HH + 64 + tx*4) = make_float4(p2.x,p2.y,p3.x,p3.y);
    }
}

// =========================================================================================
extern "C" void kernel_launch(void* const* d_in, const int* in_sizes, int n_in,
                              void* d_out, int out_size){
    const float* node  = (const float*)d_in[0];
    const float* neigh = (const float*)d_in[1];
    // metadata order: node, neigh, neighbors_number(scalar), Wq, Wk, Wv, Wb, b
    int w = (n_in >= 8) ? 2 : 1;
    const float* Wq = (const float*)d_in[w+1];
    const float* Wk = (const float*)d_in[w+2];
    const float* Wv = (const float*)d_in[w+3];
    const float* Wb = (const float*)d_in[w+4];
    const float* bv = (const float*)d_in[w+5];

    float* out = (float*)d_out;
    const long long O_ELEMS = (long long)NPAIRS*TT*HH;   // 35,651,584
    const long long A_ELEMS = (long long)NPAIRS*TT*TT;   // 17,825,792
    float* Aout = ((long long)out_size >= O_ELEMS + A_ELEMS) ? (out + O_ELEMS) : nullptr;

    const int VO_SMEM = (128*LDT + 4*16*LDT) * (int)sizeof(float);  // 101,376 B
    cudaFuncSetAttribute(kernel_VO, cudaFuncAttributeMaxDynamicSharedMemorySize, VO_SMEM);

    dim3 thr(256);
    sgemm_flat<0><<<dim3(64,2), thr>>>(node, Wq);        // g_q  = node @ Wq^T
    sgemm_flat<1><<<dim3(64,2), thr>>>(nullptr, Wb);     // g_t2 = g_q @ Wb
    sgemm_flat<2><<<dim3(64,2), thr>>>(nullptr, Wk);     // g_P  = g_t2 @ Wk
    kernel_S <<<dim3(NPAIRS,1), thr>>>(node, neigh, bv, Aout);
    kernel_VO<<<dim3(NPAIRS,2), thr, VO_SMEM>>>(node, neigh, Wv, Aout, out);
}

// round 11
// speedup vs baseline: 1.1570x; 1.1570x over previous
#include <cuda_runtime.h>
#include <cstdint>

typedef unsigned long long ull;

#define BB 64
#define NN 16
#define TT 128
#define HH 256
#define NP1 17
#define NPAIRS (BB*NP1)   // 1088
#define LDT 132           // padded smem row stride for SIMT kernels

// ---------------- scratch (static device globals; no runtime allocation) ----------------
__device__ float g_q  [BB*TT*HH];
__device__ float g_t2 [BB*TT*HH];
__device__ float g_P  [BB*TT*HH];
__device__ float g_Afb[(size_t)NPAIRS*TT*TT];

// =================== PTX helpers (baseline ISA only — no tcgen05 on this target) ========
__device__ __forceinline__ uint32_t smem_u32(const void* p){
    uint32_t a;
    asm("{ .reg .u64 t; cvta.to.shared.u64 t, %1; cvt.u32.u64 %0, t; }" : "=r"(a) : "l"(p));
    return a;
}
// pack_bf(a,b): 32-bit word, low16 = bf16(a), high16 = bf16(b)
__device__ __forceinline__ uint32_t pack_bf(float a, float b){
    uint32_t r;
    asm("cvt.rn.satfinite.bf16x2.f32 %0, %1, %2;" : "=r"(r) : "f"(b), "f"(a));
    return r;
}
__device__ __forceinline__ void ldsm4(uint32_t r[4], uint32_t addr){
    asm volatile("ldmatrix.sync.aligned.m8n8.x4.shared.b16 {%0,%1,%2,%3}, [%4];"
        : "=r"(r[0]), "=r"(r[1]), "=r"(r[2]), "=r"(r[3]) : "r"(addr));
}
__device__ __forceinline__ void mma_bf16(float c[4], const uint32_t a[4],
                                         uint32_t b0, uint32_t b1){
    asm volatile(
        "mma.sync.aligned.m16n8k16.row.col.f32.bf16.bf16.f32 "
        "{%0,%1,%2,%3}, {%4,%5,%6,%7}, {%8,%9}, {%0,%1,%2,%3};"
        : "+f"(c[0]), "+f"(c[1]), "+f"(c[2]), "+f"(c[3])
        : "r"(a[0]), "r"(a[1]), "r"(a[2]), "r"(a[3]), "r"(b0), "r"(b1));
}

// convert a [128 rows x 64 cols] fp32 tile into (hi, lo) bf16 swizzled tiles.
// tile layout: byte = row*128 + col*2, XOR-swizzled by ((row&7)<<4) -> conflict-free ldmatrix.
__device__ __forceinline__ void cvt_tile(char* th, char* tl, const float* __restrict__ src,
                                         int ld, int tid){
    int row = tid >> 1;
    int c0  = (tid & 1) * 32;
    const float* s = src + (size_t)row*ld + c0;
    #pragma unroll
    for (int j = 0; j < 8; ++j){
        float4 v = *(const float4*)(s + j*4);
        uint32_t h0 = pack_bf(v.x, v.y), h1 = pack_bf(v.z, v.w);
        float lx = v.x - __uint_as_float(h0 << 16);
        float ly = v.y - __uint_as_float(h0 & 0xffff0000u);
        float lz = v.z - __uint_as_float(h1 << 16);
        float lw = v.w - __uint_as_float(h1 & 0xffff0000u);
        uint32_t l0 = pack_bf(lx, ly), l1 = pack_bf(lz, lw);
        uint32_t boff = (uint32_t)row*128u + (uint32_t)(c0 + j*4)*2u;
        uint32_t sw = boff ^ ((boff >> 3) & 0x70u);
        *(ull*)(th + sw) = (ull)h0 | ((ull)h1 << 32);
        *(ull*)(tl + sw) = (ull)l0 | ((ull)l1 << 32);
    }
}

__device__ __forceinline__ const float* pair_base(int p, const float* node, const float* neigh){
    int b = p / NP1, n = p % NP1;
    return (n == 0) ? node  + (size_t)b*TT*HH
                    : neigh + (size_t)(b*NN + (n-1))*TT*HH;
}

// one K=64 slab of split MMAs for a warp: A strip rows [16w,16w+16), all 128 n.
// acc[16][4]: n-tile nt covers cols nt*8..nt*8+7.
__device__ __forceinline__ void slab_mma_warp(float acc[16][4],
                                              uint32_t uAH, uint32_t uAL,
                                              uint32_t uBH, uint32_t uBL,
                                              int w, int l){
    int r8 = l & 7;
    int rowA = 16*w + ((l>>3)&1)*8 + r8;          // A ldmatrix row
    uint32_t aBase = (uint32_t)rowA*128u;
    uint32_t aSwx  = (uint32_t)(rowA & 7) << 4;
    uint32_t aKadd = ((l>>4)&1) * 16;             // +8 bf16 for matrices 2,3
    int rowBl = ((l>>4)&1)*8 + r8;                // B ldmatrix row (local)
    uint32_t bKadd = ((l>>3)&1) * 16;
    #pragma unroll
    for (int ks = 0; ks < 4; ++ks){
        uint32_t akb = (uint32_t)ks*32 + aKadd;
        uint32_t aoff = aBase + (akb ^ aSwx);
        uint32_t ah[4], al[4];
        ldsm4(ah, uAH + aoff);
        ldsm4(al, uAL + aoff);
        uint32_t bkb = (uint32_t)ks*32 + bKadd;
        #pragma unroll
        for (int ntp = 0; ntp < 8; ++ntp){
            int rowB = ntp*16 + rowBl;
            uint32_t boff = (uint32_t)rowB*128u + (bkb ^ ((uint32_t)(rowB & 7) << 4));
            uint32_t bh[4], bl[4];
            ldsm4(bh, uBH + boff);
            ldsm4(bl, uBL + boff);
            mma_bf16(acc[2*ntp],   ah, bh[0], bh[1]);
            mma_bf16(acc[2*ntp],   ah, bl[0], bl[1]);
            mma_bf16(acc[2*ntp],   al, bh[0], bh[1]);
            mma_bf16(acc[2*ntp+1], ah, bh[2], bh[3]);
            mma_bf16(acc[2*ntp+1], ah, bl[2], bl[3]);
            mma_bf16(acc[2*ntp+1], al, bh[2], bh[3]);
        }
    }
}

// =================== SIMT fp32 machinery (K1..K3 weight chain) ===========================
__device__ __forceinline__ void fma2(ull& d, ull a, ull b){
    asm("fma.rn.f32x2 %0, %1, %2, %0;" : "+l"(d) : "l"(a), "l"(b));
}
__device__ __forceinline__ ull pk2(float x, float y){
    ull r; asm("mov.b64 %0, {%1, %2};" : "=l"(r) : "f"(x), "f"(y)); return r;
}
__device__ __forceinline__ float2 upk(ull v){
    float2 f; asm("mov.b64 {%0, %1}, %2;" : "=f"(f.x), "=f"(f.y) : "l"(v)); return f;
}
struct F8 { float4 a, b; };
__device__ __forceinline__ F8 ldg_T(const float* __restrict__ src, int ld, int tid){
    int c4 = (tid & 3) * 4, r = tid >> 2;
    F8 f;
    f.a = *(const float4*)(src + (size_t)r*ld + c4);
    f.b = *(const float4*)(src + (size_t)(r+64)*ld + c4);
    return f;
}
__device__ __forceinline__ void sts_T(float (*dst)[LDT], F8 f, int tid){
    int c4 = (tid & 3) * 4, r = tid >> 2;
    dst[c4+0][r]    = f.a.x; dst[c4+1][r]    = f.a.y;
    dst[c4+2][r]    = f.a.z; dst[c4+3][r]    = f.a.w;
    dst[c4+0][r+64] = f.b.x; dst[c4+1][r+64] = f.b.y;
    dst[c4+2][r+64] = f.b.z; dst[c4+3][r+64] = f.b.w;
}
__device__ __forceinline__ F8 ldg_D(const float* __restrict__ src, int ld, int tid){
    int n4 = (tid & 15) * 4, k = tid >> 4;
    F8 f;
    f.a = *(const float4*)(src + (size_t)k*ld + n4);
    f.b = *(const float4*)(src + (size_t)k*ld + n4 + 64);
    return f;
}
__device__ __forceinline__ void sts_D(float (*dst)[LDT], F8 f, int tid){
    int n4 = (tid & 15) * 4, k = tid >> 4;
    *(float4*)(&dst[k][n4])      = f.a;
    *(float4*)(&dst[k][n4 + 64]) = f.b;
}
__device__ __forceinline__ void mm16(ull acc[8][4], const float (*As)[LDT],
                                     const float (*Bs)[LDT], int tx, int ty){
    #pragma unroll
    for (int k = 0; k < 16; ++k){
        float4 a0 = *(const float4*)(&As[k][ty*4]);
        float4 a1 = *(const float4*)(&As[k][64+ty*4]);
        float4 b0 = *(const float4*)(&Bs[k][tx*4]);
        float4 b1 = *(const float4*)(&Bs[k][64+tx*4]);
        ull bb0 = pk2(b0.x,b0.y), bb1 = pk2(b0.z,b0.w);
        ull bb2 = pk2(b1.x,b1.y), bb3 = pk2(b1.z,b1.w);
        float av[8] = {a0.x,a0.y,a0.z,a0.w,a1.x,a1.y,a1.z,a1.w};
        #pragma unroll
        for (int i = 0; i < 8; ++i){
            ull ad = pk2(av[i], av[i]);
            fma2(acc[i][0], ad, bb0);
            fma2(acc[i][1], ad, bb1);
            fma2(acc[i][2], ad, bb2);
            fma2(acc[i][3], ad, bb3);
        }
    }
}
__device__ __forceinline__ int row_of(int i, int ty){
    return (i < 4) ? (ty*4 + i) : (64 + ty*4 + (i-4));
}

// ================= K1..K3: flat [8192,256] x [256,256] GEMM chain (SIMT) =================
template<int STEP>
__global__ void __launch_bounds__(256, 2) sgemm_flat(const float* __restrict__ Ain,
                                                     const float* __restrict__ W){
    __shared__ __align__(16) float As[2][16][LDT], Bs[2][16][LDT];
    int tid = threadIdx.x, tx = tid & 15, ty = tid >> 4;
    const float* A = (STEP == 0) ? Ain : (STEP == 1 ? g_q : g_t2);
    float*       C = (STEP == 0) ? g_q : (STEP == 1 ? g_t2 : g_P);
    const float* Ab = A + (size_t)blockIdx.x * 128 * HH;
    int n0 = blockIdx.y * 128;
    const float* Bb = (STEP == 0) ? W + (size_t)n0*HH : W + n0;

    ull acc[8][4];
    #pragma unroll
    for (int i=0;i<8;i++){ acc[i][0]=acc[i][1]=acc[i][2]=acc[i][3]=0ULL; }

    F8 ra = ldg_T(Ab, HH, tid);
    F8 rb = (STEP == 0) ? ldg_T(Bb, HH, tid) : ldg_D(Bb, HH, tid);
    sts_T(As[0], ra, tid);
    if (STEP == 0) sts_T(Bs[0], rb, tid); else sts_D(Bs[0], rb, tid);
    __syncthreads();

    #pragma unroll 2
    for (int s = 0; s < 16; ++s){
        if (s < 15){
            ra = ldg_T(Ab + (s+1)*16, HH, tid);
            rb = (STEP == 0) ? ldg_T(Bb + (s+1)*16, HH, tid)
                             : ldg_D(Bb + (size_t)(s+1)*16*HH, HH, tid);
        }
        mm16(acc, As[s&1], Bs[s&1], tx, ty);
        if (s < 15){
            sts_T(As[(s+1)&1], ra, tid);
            if (STEP == 0) sts_T(Bs[(s+1)&1], rb, tid); else sts_D(Bs[(s+1)&1], rb, tid);
        }
        __syncthreads();
    }

    float* Cb = C + (size_t)blockIdx.x*128*HH + n0;
    #pragma unroll
    for (int i=0;i<8;i++){
        int row = row_of(i, ty);
        float2 p0=upk(acc[i][0]), p1=upk(acc[i][1]), p2=upk(acc[i][2]), p3=upk(acc[i][3]);
        *(float4*)(Cb + (size_t)row*HH + tx*4)      = make_float4(p0.x,p0.y,p1.x,p1.y);
        *(float4*)(Cb + (size_t)row*HH + 64 + tx*4) = make_float4(p2.x,p2.y,p3.x,p3.y);
    }
}

// ================= K4 (tensor): S = P_b @ X_p^T (+bias) -> softmax -> A ==================
__global__ void __launch_bounds__(256) kernel_S_tc(const float* __restrict__ node,
                                                   const float* __restrict__ neigh,
                                                   const float* __restrict__ bias,
                                                   float* Aout){
    extern __shared__ char sm[];
    char* base = (char*)(((uintptr_t)sm + 1023) & ~(uintptr_t)1023);
    char* tPH = base;            char* tPL = base + 16384;
    char* tXH = base + 32768;    char* tXL = base + 49152;
    uint32_t uPH = smem_u32(tPH), uPL = smem_u32(tPL);
    uint32_t uXH = smem_u32(tXH), uXL = smem_u32(tXL);

    int tid = threadIdx.x, w = tid >> 5, l = tid & 31;
    int p = blockIdx.x, b = p / NP1;
    const float* P = g_P + (size_t)b*TT*HH;
    const float* X = pair_base(p, node, neigh);
    float* Ao = Aout ? Aout : g_Afb;

    float acc[16][4];
    #pragma unroll
    for (int i=0;i<16;i++){ acc[i][0]=acc[i][1]=acc[i][2]=acc[i][3]=0.f; }

    for (int s = 0; s < 4; ++s){
        cvt_tile(tPH, tPL, P + s*64, HH, tid);
        cvt_tile(tXH, tXL, X + s*64, HH, tid);
        __syncthreads();
        slab_mma_warp(acc, uPH, uPL, uXH, uXL, w, l);
        __syncthreads();
    }

    // epilogue: lane l owns rows r0 = 16w + (l>>2), r1 = r0+8 ; cols nt*8 + (l&3)*2 (+1)
    int q = l & 3;
    int r0 = 16*w + (l>>2), r1 = r0 + 8;
    #pragma unroll
    for (int nt = 0; nt < 16; ++nt){
        float2 bb = *(const float2*)(bias + nt*8 + q*2);
        acc[nt][0] += bb.x; acc[nt][1] += bb.y;
        acc[nt][2] += bb.x; acc[nt][3] += bb.y;
    }
    float m0 = -1e30f, m1 = -1e30f;
    #pragma unroll
    for (int nt = 0; nt < 16; ++nt){
        m0 = fmaxf(m0, fmaxf(acc[nt][0], acc[nt][1]));
        m1 = fmaxf(m1, fmaxf(acc[nt][2], acc[nt][3]));
    }
    m0 = fmaxf(m0, __shfl_xor_sync(0xffffffffu, m0, 1));
    m0 = fmaxf(m0, __shfl_xor_sync(0xffffffffu, m0, 2));
    m1 = fmaxf(m1, __shfl_xor_sync(0xffffffffu, m1, 1));
    m1 = fmaxf(m1, __shfl_xor_sync(0xffffffffu, m1, 2));
    float s0 = 0.f, s1 = 0.f;
    #pragma unroll
    for (int nt = 0; nt < 16; ++nt){
        acc[nt][0] = __expf(acc[nt][0] - m0); s0 += acc[nt][0];
        acc[nt][1] = __expf(acc[nt][1] - m0); s0 += acc[nt][1];
        acc[nt][2] = __expf(acc[nt][2] - m1); s1 += acc[nt][2];
        acc[nt][3] = __expf(acc[nt][3] - m1); s1 += acc[nt][3];
    }
    s0 += __shfl_xor_sync(0xffffffffu, s0, 1);
    s0 += __shfl_xor_sync(0xffffffffu, s0, 2);
    s1 += __shfl_xor_sync(0xffffffffu, s1, 1);
    s1 += __shfl_xor_sync(0xffffffffu, s1, 2);
    float i0 = 1.f / s0, i1 = 1.f / s1;
    float* Ap = Ao + (size_t)p*TT*TT;
    #pragma unroll
    for (int nt = 0; nt < 16; ++nt){
        *(float2*)(Ap + (size_t)r0*TT + nt*8 + q*2) = make_float2(acc[nt][0]*i0, acc[nt][1]*i0);
        *(float2*)(Ap + (size_t)r1*TT + nt*8 + q*2) = make_float2(acc[nt][2]*i1, acc[nt][3]*i1);
    }
}

// ================= K5 (tensor): Vt[c,s] = Wv_chunk @ X^T ; O = A @ Vt^T ==================
__global__ void __launch_bounds__(256) kernel_VO_tc(const float* __restrict__ node,
                                                    const float* __restrict__ neigh,
                                                    const float* __restrict__ Wv,
                                                    const float* Ain,
                                                    float* __restrict__ Out){
    extern __shared__ char sm[];
    char* base = (char*)(((uintptr_t)sm + 1023) & ~(uintptr_t)1023);
    char* T0 = base;          char* T1 = base + 16384;
    char* T2 = base + 32768;  char* T3 = base + 49152;
    char* T4 = base + 65536;  char* T5 = base + 81920;
    uint32_t u0 = smem_u32(T0), u1 = smem_u32(T1), u2 = smem_u32(T2);
    uint32_t u3 = smem_u32(T3), u4 = smem_u32(T4), u5 = smem_u32(T5);

    int tid = threadIdx.x, w = tid >> 5, l = tid & 31;
    int p = blockIdx.x;
    int n0 = blockIdx.y * 128;
    const float* X  = pair_base(p, node, neigh);
    const float* Wc = Wv + (size_t)n0*HH;
    const float* Ap = (Ain ? Ain : (const float*)g_Afb) + (size_t)p*TT*TT;

    float acc[16][4];
    #pragma unroll
    for (int i=0;i<16;i++){ acc[i][0]=acc[i][1]=acc[i][2]=acc[i][3]=0.f; }

    // ---- Phase 1: D1[c, s] = sum_h Wv[n0+c, h] * X[s, h]  (A=Wc strip, B=X) ----
    for (int s = 0; s < 4; ++s){
        cvt_tile(T0, T1, Wc + s*64, HH, tid);
        cvt_tile(T2, T3, X  + s*64, HH, tid);
        __syncthreads();
        slab_mma_warp(acc, u0, u1, u2, u3, w, l);
        __syncthreads();
    }

    // ---- Phase 2: split-convert D1 into persistent Vt tiles ----
    // Vt stored [c][s_local] per s-half: hi/lo s0-63 -> T0/T1 ; s64-127 -> T2/T3
    {
        int q = l & 3;
        int c0 = 16*w + (l>>2), c1 = c0 + 8;
        #pragma unroll
        for (int nt = 0; nt < 16; ++nt){
            int s = nt*8 + q*2;                    // even; pair stays in one half
            char* th = (s < 64) ? T0 : T2;
            char* tl = (s < 64) ? T1 : T3;
            int sl = s & 63;
            #pragma unroll
            for (int h = 0; h < 2; ++h){
                int c = h ? c1 : c0;
                float a = acc[nt][2*h], bq = acc[nt][2*h+1];
                uint32_t hi = pack_bf(a, bq);
                float la = a  - __uint_as_float(hi << 16);
                float lb = bq - __uint_as_float(hi & 0xffff0000u);
                uint32_t lo = pack_bf(la, lb);
                uint32_t boff = (uint32_t)c*128u + (uint32_t)sl*2u;
                uint32_t sw = boff ^ ((uint32_t)(c & 7) << 4);
                *(uint32_t*)(th + sw) = hi;
                *(uint32_t*)(tl + sw) = lo;
            }
            acc[nt][0]=acc[nt][1]=acc[nt][2]=acc[nt][3]=0.f;
        }
    }
    __syncthreads();

    // ---- Phase 3: D2[t, c] = sum_s A[t, s] * Vt[c, s]  (A staged in T4/T5, B=Vt) ----
    for (int s2 = 0; s2 < 2; ++s2){
        cvt_tile(T4, T5, Ap + s2*64, TT, tid);
        __syncthreads();
        slab_mma_warp(acc, u4, u5, s2 ? u2 : u0, s2 ? u3 : u1, w, l);
        __syncthreads();
    }

    // ---- Phase 4: store O[t, n0 + c] ----
    {
        int q = l & 3;
        int t0 = 16*w + (l>>2), t1 = t0 + 8;
        float* Ob = Out + (size_t)p*TT*HH + n0;
        #pragma unroll
        for (int nt = 0; nt < 16; ++nt){
            *(float2*)(Ob + (size_t)t0*HH + nt*8 + q*2) = make_float2(acc[nt][0], acc[nt][1]);
            *(float2*)(Ob + (size_t)t1*HH + nt*8 + q*2) = make_float2(acc[nt][2], acc[nt][3]);
        }
    }
}

// =========================================================================================
extern "C" void kernel_launch(void* const* d_in, const int* in_sizes, int n_in,
                              void* d_out, int out_size){
    const float* node  = (const float*)d_in[0];
    const float* neigh = (const float*)d_in[1];
    int w = (n_in >= 8) ? 2 : 1;
    const float* Wq = (const float*)d_in[w+1];
    const float* Wk = (const float*)d_in[w+2];
    const float* Wv = (const float*)d_in[w+3];
    const float* Wb = (const float*)d_in[w+4];
    const float* bv = (const float*)d_in[w+5];

    float* out = (float*)d_out;
    const long long O_ELEMS = (long long)NPAIRS*TT*HH;
    const long long A_ELEMS = (long long)NPAIRS*TT*TT;
    float* Aout = ((long long)out_size >= O_ELEMS + A_ELEMS) ? (out + O_ELEMS) : nullptr;

    const int S_SMEM  = 4*16384 + 1024;   // 4 bf16 tiles + align pad
    const int VO_SMEM = 6*16384 + 1024;   // 6 bf16 tiles + align pad
    cudaFuncSetAttribute(kernel_S_tc,  cudaFuncAttributeMaxDynamicSharedMemorySize, S_SMEM);
    cudaFuncSetAttribute(kernel_VO_tc, cudaFuncAttributeMaxDynamicSharedMemorySize, VO_SMEM);

    dim3 thr(256);
    sgemm_flat<0><<<dim3(64,2), thr>>>(node, Wq);        // g_q  = node @ Wq^T
    sgemm_flat<1><<<dim3(64,2), thr>>>(nullptr, Wb);     // g_t2 = g_q @ Wb
    sgemm_flat<2><<<dim3(64,2), thr>>>(nullptr, Wk);     // g_P  = g_t2 @ Wk
    kernel_S_tc <<<dim3(NPAIRS,1), thr, S_SMEM>>>(node, neigh, bv, Aout);
    kernel_VO_tc<<<dim3(NPAIRS,2), thr, VO_SMEM>>>(node, neigh, Wv, Aout, out);
}